// round 10
// baseline (speedup 1.0000x reference)
#include <cuda_runtime.h>
#include <cuda_bf16.h>

#define NB 32
#define TC 256
#define NVOCAB 100
#define ND 384
#define DCH 128          // dims per block (3-way D split)
#define NWARPS 16
#define NTILES 3
#define MAXT 2048
#define FB 4             // frames per warp per group
#define RWIN 26          // |t-center|>26 => z>=6.5 => normalized w < ~2e-9
#define WMAX 56          // (FB-1)+2*RWIN+1 = 56
#define PWARPS 8

__device__ float g_center[NB][TC];
__device__ float g_invsig[NB][TC];
__device__ float g_wfac[NB][TC];
__device__ int   g_roff[NB][TC];     // text row * DCH
__device__ int   g_totdur[NB];
__device__ int   g_fidx[NB][MAXT];

// ---------------- Phase 1: warp-per-batch scan + params ----------------
__global__ __launch_bounds__(PWARPS * 32)
void ge_prep_kernel(const int* __restrict__ text,
                    const int* __restrict__ durs) {
    int wid = threadIdx.x >> 5, lane = threadIdx.x & 31;
    int b = blockIdx.x * PWARPS + wid;
    if (b >= NB) return;

    const int4* dp = (const int4*)(durs + b * TC + lane * 8);
    int4 da = dp[0], db = dp[1];
    int dv[8] = {da.x, da.y, da.z, da.w, db.x, db.y, db.z, db.w};
    const int4* tp = (const int4*)(text + b * TC + lane * 8);
    int4 ta = tp[0], tb = tp[1];
    int tv[8] = {ta.x, ta.y, ta.z, ta.w, tb.x, tb.y, tb.z, tb.w};

    int lanesum = 0;
    #pragma unroll
    for (int i = 0; i < 8; i++) lanesum += dv[i];
    int incl = lanesum;
    #pragma unroll
    for (int off = 1; off < 32; off <<= 1) {
        int v = __shfl_up_sync(0xffffffffu, incl, off);
        if (lane >= off) incl += v;
    }
    int total = __shfl_sync(0xffffffffu, incl, 31);
    int run = incl - lanesum;          // exclusive prefix for this lane

    #pragma unroll
    for (int i = 0; i < 8; i++) {
        int c = lane * 8 + i;
        int d = dv[i];
        float df = (float)d;
        float sig = df * 0.5f + 1e-6f;
        float is = 1.0f / sig;
        g_center[b][c] = (float)run + df * 0.5f;
        g_invsig[b][c] = is;
        g_wfac[b][c]   = 0.3989422804014327f * is;
        g_roff[b][c]   = tv[i] * DCH;
        for (int f = run; f < run + d; f++) g_fidx[b][f] = c;
        run += d;
    }
    if (lane == 31) g_totdur[b] = total;
}

__device__ __forceinline__ void fma2(unsigned long long& acc,
                                     unsigned long long a,
                                     unsigned long long b) {
    asm("fma.rn.f32x2 %0, %1, %2, %0;" : "+l"(acc) : "l"(a), "l"(b));
}

// ---------------- Phase 2: fused weights + gather (3-way D split) ----------------
// Lane owns float4 at h*128 + lane*4: conflict-free LDS, coalesced STG.
__global__ __launch_bounds__(NWARPS * 32, 2)
void ge_main_kernel(const float* __restrict__ embed,
                    float* __restrict__ out, int Tt) {
    extern __shared__ float smem[];
    float* semb     = smem;                      // NVOCAB*DCH (51.2 KB)
    float* s_center = semb + NVOCAB * DCH;       // 256
    float* s_invsig = s_center + TC;             // 256
    float* s_wfac   = s_invsig + TC;             // 256
    int*   s_roff   = (int*)(s_wfac + TC);       // 256
    int*   s_fidx   = s_roff + TC;               // MAXT
    float* s_wbuf   = (float*)(s_fidx + MAXT);   // NWARPS * WMAX * 8 (dup'd weights)
    int*   s_cbuf   = (int*)(s_wbuf + NWARPS * WMAX * 8); // NWARPS * WMAX

    int tid = threadIdx.x;
    int b = blockIdx.y;
    int h = blockIdx.z;
    int totdur = g_totdur[b];

    for (int i = tid; i < NVOCAB * 32; i += NWARPS * 32) {
        int v = i >> 5, c = i & 31;
        ((float4*)(semb + v * DCH))[c] =
            *((const float4*)(embed + v * ND + h * DCH) + c);
    }
    if (tid < TC) {
        s_center[tid] = g_center[b][tid];
        s_invsig[tid] = g_invsig[b][tid];
        s_wfac[tid]   = g_wfac[b][tid];
        s_roff[tid]   = g_roff[b][tid];
    }
    for (int f = tid; f < totdur; f += NWARPS * 32) s_fidx[f] = g_fidx[b][f];
    __syncthreads();

    int wid = tid >> 5, lane = tid & 31;
    float* wrow8 = s_wbuf + wid * (WMAX * 8);    // stride 8 floats per char
    int*   coffw = s_cbuf + wid * WMAX;

    for (int t0 = (blockIdx.x * NWARPS + wid) * FB; t0 < Tt;
         t0 += NTILES * NWARPS * FB) {

        int nvalid = totdur - t0;
        if (nvalid > FB) nvalid = FB;

        if (nvalid <= 0) {                       // whole group time-pad -> embed[0]
            float4 e0 = ((const float4*)semb)[lane];
            #pragma unroll
            for (int f = 0; f < FB; f++) {
                int t = t0 + f;
                if (t >= Tt) break;
                ((float4*)(out + ((size_t)b * Tt + t) * ND + h * DCH))[lane] = e0;
            }
            continue;
        }

        int lo = s_fidx[max(t0 - RWIN, 0)];
        int hi = s_fidx[min(t0 + FB - 1 + RWIN, totdur - 1)] + 1;
        int win = hi - lo;

        // ---- weight pass (raw weights; <=2 lane-chunks) ----
        float tt = (float)t0 + 0.5f;
        float l0 = 0.f, l1 = 0.f, l2 = 0.f, l3 = 0.f;
        for (int j = lane; j < win; j += 32) {
            int c = lo + j;
            float is = s_invsig[c];
            float z0 = (tt - s_center[c]) * is;
            float z1 = z0 + is, z2 = z1 + is, z3 = z2 + is;
            float wf = s_wfac[c];
            float w0 = __expf(-0.5f * z0 * z0) * wf;
            float w1 = __expf(-0.5f * z1 * z1) * wf;
            float w2 = __expf(-0.5f * z2 * z2) * wf;
            float w3 = __expf(-0.5f * z3 * z3) * wf;
            if (1 >= nvalid) w1 = 0.f;
            if (2 >= nvalid) w2 = 0.f;
            if (3 >= nvalid) w3 = 0.f;
            *(float4*)&wrow8[j * 8] = make_float4(w0, w1, w2, w3);
            l0 += w0; l1 += w1; l2 += w2; l3 += w3;
        }
        __syncwarp();
        #pragma unroll
        for (int off = 16; off; off >>= 1) {
            l0 += __shfl_xor_sync(0xffffffffu, l0, off);
            l1 += __shfl_xor_sync(0xffffffffu, l1, off);
            l2 += __shfl_xor_sync(0xffffffffu, l2, off);
            l3 += __shfl_xor_sync(0xffffffffu, l3, off);
        }
        float i0 = 1.0f / (l0 + 1e-6f), i1 = 1.0f / (l1 + 1e-6f);
        float i2 = 1.0f / (l2 + 1e-6f), i3 = 1.0f / (l3 + 1e-6f);

        // ---- normalize + compact, storing DUPLICATED weight pairs ----
        int nact = 0;
        for (int base = 0; base < win; base += 32) {
            int j = base + lane;
            float4 wv;
            int off = 0;
            bool act = false;
            if (j < win) {
                wv = *(float4*)&wrow8[j * 8];
                wv.x *= i0; wv.y *= i1; wv.z *= i2; wv.w *= i3;
                act = (wv.x > 1e-8f) | (wv.y > 1e-8f) |
                      (wv.z > 1e-8f) | (wv.w > 1e-8f);
                off = s_roff[lo + j];
            }
            unsigned mask = __ballot_sync(0xffffffffu, act);
            __syncwarp();
            if (act) {
                int pos = nact + __popc(mask & ((1u << lane) - 1u));
                *(float4*)&wrow8[pos * 8]     = make_float4(wv.x, wv.x, wv.y, wv.y);
                *(float4*)&wrow8[pos * 8 + 4] = make_float4(wv.z, wv.z, wv.w, wv.w);
                coffw[pos] = off;
            }
            nact += __popc(mask);
        }
        __syncwarp();

        // ---- branch-free FMA pass: 12 slots/char ----
        unsigned long long A[FB][2];
        #pragma unroll
        for (int f = 0; f < FB; f++) { A[f][0] = 0ULL; A[f][1] = 0ULL; }

        for (int k = 0; k < nact; k++) {
            ulonglong2 W01 = *(const ulonglong2*)&wrow8[k * 8];     // {W0,W1}
            ulonglong2 W23 = *(const ulonglong2*)&wrow8[k * 8 + 4]; // {W2,W3}
            int off = coffw[k];
            ulonglong2 p = ((const ulonglong2*)(semb + off))[lane];
            fma2(A[0][0], W01.x, p.x); fma2(A[0][1], W01.x, p.y);
            fma2(A[1][0], W01.y, p.x); fma2(A[1][1], W01.y, p.y);
            fma2(A[2][0], W23.x, p.x); fma2(A[2][1], W23.x, p.y);
            fma2(A[3][0], W23.y, p.x); fma2(A[3][1], W23.y, p.y);
        }
        __syncwarp();   // wrow8/coffw reused next group

        // ---- write (weights pre-normalized; coalesced 512B) ----
        #pragma unroll
        for (int f = 0; f < FB; f++) {
            int t = t0 + f;
            if (t >= Tt) break;
            float4* o = (float4*)(out + ((size_t)b * Tt + t) * ND + h * DCH);
            if (f < nvalid) {
                union { unsigned long long u[2]; float4 v; } cv;
                cv.u[0] = A[f][0];
                cv.u[1] = A[f][1];
                o[lane] = cv.v;
            } else {      // time-pad frame -> embed[0]
                o[lane] = ((const float4*)semb)[lane];
            }
        }
    }
}

extern "C" void kernel_launch(void* const* d_in, const int* in_sizes, int n_in,
                              void* d_out, int out_size) {
    const int*   text  = (const int*)d_in[0];
    const int*   durs  = (const int*)d_in[1];
    const float* embed = (const float*)d_in[2];
    float* out = (float*)d_out;

    int Tt = out_size / (NB * ND);

    size_t smem_bytes = (size_t)(NVOCAB * DCH + 3 * TC) * sizeof(float)
                        + (size_t)(TC + MAXT) * sizeof(int)
                        + (size_t)(NWARPS * WMAX * 8) * sizeof(float)
                        + (size_t)(NWARPS * WMAX) * sizeof(int);
    cudaFuncSetAttribute(ge_main_kernel,
                         cudaFuncAttributeMaxDynamicSharedMemorySize,
                         (int)smem_bytes);

    ge_prep_kernel<<<(NB + PWARPS - 1) / PWARPS, PWARPS * 32>>>(text, durs);
    ge_main_kernel<<<dim3(NTILES, NB, 3), NWARPS * 32, smem_bytes>>>(embed, out, Tt);
}

// round 11
// speedup vs baseline: 1.3022x; 1.3022x over previous
#include <cuda_runtime.h>
#include <cuda_bf16.h>

#define NB 32
#define TC 256
#define NVOCAB 100
#define ND 384
#define DCH 128          // dims per block (3-way D split)
#define NWARPS 16
#define NTILES 3
#define MAXT 2048
#define FB 4             // frames per warp per group
#define RWIN 26          // |t-center|>26 => z>=6.5 => normalized w < ~2e-9
#define WMAX 56          // (FB-1)+2*RWIN+1 = 56

__device__ float g_center[NB][TC];
__device__ float g_invsig[NB][TC];
__device__ float g_wfac[NB][TC];
__device__ int   g_roff[NB][TC];     // text row * DCH
__device__ int   g_totdur[NB];
__device__ int   g_fidx[NB][MAXT];

// ---------------- Phase 1: block-per-batch scan + params (R8 version) ----------------
__global__ void ge_prep_kernel(const int* __restrict__ text,
                               const int* __restrict__ durs) {
    __shared__ int s[TC];
    int b = blockIdx.x, c = threadIdx.x;
    int d = durs[b * TC + c];
    s[c] = d;
    __syncthreads();
    #pragma unroll
    for (int off = 1; off < TC; off <<= 1) {
        int v = (c >= off) ? s[c - off] : 0;
        __syncthreads();
        s[c] += v;
        __syncthreads();
    }
    int incl = s[c];
    int start = incl - d;
    float df = (float)d;
    float sig = df * 0.5f + 1e-6f;
    float is = 1.0f / sig;
    g_center[b][c] = (float)start + df * 0.5f;
    g_invsig[b][c] = is;
    g_wfac[b][c]   = 0.3989422804014327f * is;
    g_roff[b][c]   = text[b * TC + c] * DCH;
    for (int f = start; f < incl; f++) g_fidx[b][f] = c;
    if (c == TC - 1) g_totdur[b] = incl;
}

__device__ __forceinline__ void fma2(unsigned long long& acc,
                                     unsigned long long a,
                                     unsigned long long b) {
    asm("fma.rn.f32x2 %0, %1, %2, %0;" : "+l"(acc) : "l"(a), "l"(b));
}

// ---------------- Phase 2: fused weights + gather (3-way D split) ----------------
// Lane owns float4 at h*128 + lane*4: conflict-free LDS, coalesced STG.
// All per-warp scratch buffers use 16B lane stride (conflict-free STS.128).
__global__ __launch_bounds__(NWARPS * 32, 2)
void ge_main_kernel(const float* __restrict__ embed,
                    float* __restrict__ out, int Tt) {
    extern __shared__ float smem[];
    float* semb     = smem;                      // NVOCAB*DCH (51.2 KB)
    float* s_center = semb + NVOCAB * DCH;       // 256
    float* s_invsig = s_center + TC;             // 256
    float* s_wfac   = s_invsig + TC;             // 256
    int*   s_roff   = (int*)(s_wfac + TC);       // 256
    int*   s_fidx   = s_roff + TC;               // MAXT
    float* s_wbufA  = (float*)(s_fidx + MAXT);   // NWARPS*WMAX*4  ({w0,w0,w1,w1})
    float* s_wbufB  = s_wbufA + NWARPS * WMAX * 4; // NWARPS*WMAX*4 ({w2,w2,w3,w3})
    int*   s_cbuf   = (int*)(s_wbufB + NWARPS * WMAX * 4); // NWARPS*WMAX

    int tid = threadIdx.x;
    int b = blockIdx.y;
    int h = blockIdx.z;
    int totdur = g_totdur[b];

    for (int i = tid; i < NVOCAB * 32; i += NWARPS * 32) {
        int v = i >> 5, c = i & 31;
        ((float4*)(semb + v * DCH))[c] =
            *((const float4*)(embed + v * ND + h * DCH) + c);
    }
    if (tid < TC) {
        s_center[tid] = g_center[b][tid];
        s_invsig[tid] = g_invsig[b][tid];
        s_wfac[tid]   = g_wfac[b][tid];
        s_roff[tid]   = g_roff[b][tid];
    }
    for (int f = tid; f < totdur; f += NWARPS * 32) s_fidx[f] = g_fidx[b][f];
    __syncthreads();

    int wid = tid >> 5, lane = tid & 31;
    float* wrowA = s_wbufA + wid * (WMAX * 4);   // stride 16B per char
    float* wrowB = s_wbufB + wid * (WMAX * 4);
    int*   coffw = s_cbuf + wid * WMAX;

    for (int t0 = (blockIdx.x * NWARPS + wid) * FB; t0 < Tt;
         t0 += NTILES * NWARPS * FB) {

        int nvalid = totdur - t0;
        if (nvalid > FB) nvalid = FB;

        if (nvalid <= 0) {                       // whole group time-pad -> embed[0]
            float4 e0 = ((const float4*)semb)[lane];
            #pragma unroll
            for (int f = 0; f < FB; f++) {
                int t = t0 + f;
                if (t >= Tt) break;
                ((float4*)(out + ((size_t)b * Tt + t) * ND + h * DCH))[lane] = e0;
            }
            continue;
        }

        int lo = s_fidx[max(t0 - RWIN, 0)];
        int hi = s_fidx[min(t0 + FB - 1 + RWIN, totdur - 1)] + 1;
        int win = hi - lo;                       // <= 56: 2 lane-chunks

        // ---- weight pass (raw weights, stride-16B conflict-free) ----
        float tt = (float)t0 + 0.5f;
        float l0 = 0.f, l1 = 0.f, l2 = 0.f, l3 = 0.f;
        for (int j = lane; j < win; j += 32) {
            int c = lo + j;
            float is = s_invsig[c];
            float z0 = (tt - s_center[c]) * is;
            float z1 = z0 + is, z2 = z1 + is, z3 = z2 + is;
            float wf = s_wfac[c];
            float w0 = __expf(-0.5f * z0 * z0) * wf;
            float w1 = __expf(-0.5f * z1 * z1) * wf;
            float w2 = __expf(-0.5f * z2 * z2) * wf;
            float w3 = __expf(-0.5f * z3 * z3) * wf;
            if (1 >= nvalid) w1 = 0.f;
            if (2 >= nvalid) w2 = 0.f;
            if (3 >= nvalid) w3 = 0.f;
            *(float4*)&wrowA[j * 4] = make_float4(w0, w1, w2, w3);
            l0 += w0; l1 += w1; l2 += w2; l3 += w3;
        }
        __syncwarp();
        #pragma unroll
        for (int off = 16; off; off >>= 1) {
            l0 += __shfl_xor_sync(0xffffffffu, l0, off);
            l1 += __shfl_xor_sync(0xffffffffu, l1, off);
            l2 += __shfl_xor_sync(0xffffffffu, l2, off);
            l3 += __shfl_xor_sync(0xffffffffu, l3, off);
        }
        float i0 = 1.0f / (l0 + 1e-6f), i1 = 1.0f / (l1 + 1e-6f);
        float i2 = 1.0f / (l2 + 1e-6f), i3 = 1.0f / (l3 + 1e-6f);

        // ---- normalize + compact, writing pre-duplicated pairs ----
        int nact = 0;
        for (int base = 0; base < win; base += 32) {
            int j = base + lane;
            float4 wv;
            int off = 0;
            bool act = false;
            if (j < win) {
                wv = *(float4*)&wrowA[j * 4];
                wv.x *= i0; wv.y *= i1; wv.z *= i2; wv.w *= i3;
                act = (wv.x > 1e-8f) | (wv.y > 1e-8f) |
                      (wv.z > 1e-8f) | (wv.w > 1e-8f);
                off = s_roff[lo + j];
            }
            unsigned mask = __ballot_sync(0xffffffffu, act);
            __syncwarp();
            if (act) {
                int pos = nact + __popc(mask & ((1u << lane) - 1u));
                *(float4*)&wrowA[pos * 4] = make_float4(wv.x, wv.x, wv.y, wv.y);
                *(float4*)&wrowB[pos * 4] = make_float4(wv.z, wv.z, wv.w, wv.w);
                coffw[pos] = off;
            }
            nact += __popc(mask);
        }
        __syncwarp();

        // ---- branch-free FMA pass: 4 LDS + 8 FFMA2 per char ----
        unsigned long long A[FB][2];
        #pragma unroll
        for (int f = 0; f < FB; f++) { A[f][0] = 0ULL; A[f][1] = 0ULL; }

        for (int k = 0; k < nact; k++) {
            ulonglong2 W01 = *(const ulonglong2*)&wrowA[k * 4]; // broadcast
            ulonglong2 W23 = *(const ulonglong2*)&wrowB[k * 4]; // broadcast
            int off = coffw[k];                                  // broadcast
            ulonglong2 p = ((const ulonglong2*)(semb + off))[lane];
            fma2(A[0][0], W01.x, p.x); fma2(A[0][1], W01.x, p.y);
            fma2(A[1][0], W01.y, p.x); fma2(A[1][1], W01.y, p.y);
            fma2(A[2][0], W23.x, p.x); fma2(A[2][1], W23.x, p.y);
            fma2(A[3][0], W23.y, p.x); fma2(A[3][1], W23.y, p.y);
        }
        __syncwarp();   // buffers reused next group

        // ---- write (weights pre-normalized; coalesced 512B) ----
        #pragma unroll
        for (int f = 0; f < FB; f++) {
            int t = t0 + f;
            if (t >= Tt) break;
            float4* o = (float4*)(out + ((size_t)b * Tt + t) * ND + h * DCH);
            if (f < nvalid) {
                union { unsigned long long u[2]; float4 v; } cv;
                cv.u[0] = A[f][0];
                cv.u[1] = A[f][1];
                o[lane] = cv.v;
            } else {      // time-pad frame -> embed[0]
                o[lane] = ((const float4*)semb)[lane];
            }
        }
    }
}

extern "C" void kernel_launch(void* const* d_in, const int* in_sizes, int n_in,
                              void* d_out, int out_size) {
    const int*   text  = (const int*)d_in[0];
    const int*   durs  = (const int*)d_in[1];
    const float* embed = (const float*)d_in[2];
    float* out = (float*)d_out;

    int Tt = out_size / (NB * ND);

    size_t smem_bytes = (size_t)(NVOCAB * DCH + 3 * TC) * sizeof(float)
                        + (size_t)(TC + MAXT) * sizeof(int)
                        + (size_t)(NWARPS * WMAX * 8) * sizeof(float)
                        + (size_t)(NWARPS * WMAX) * sizeof(int);
    cudaFuncSetAttribute(ge_main_kernel,
                         cudaFuncAttributeMaxDynamicSharedMemorySize,
                         (int)smem_bytes);

    ge_prep_kernel<<<NB, TC>>>(text, durs);
    ge_main_kernel<<<dim3(NTILES, NB, 3), NWARPS * 32, smem_bytes>>>(embed, out, Tt);
}

// round 12
// speedup vs baseline: 1.5319x; 1.1764x over previous
#include <cuda_runtime.h>
#include <cuda_bf16.h>

#define NB 32
#define TC 256
#define NVOCAB 100
#define ND 384
#define DCH 128          // dims per block (3-way D split)
#define NWARPS 16
#define NTILES 3
#define MAXT 2048
#define FB 4             // frames per warp per group
#define RWIN 26          // |t-center|>26 => z>=6.5 => normalized w < ~1e-9
#define WMAX 56          // (FB-1)+2*RWIN+1 = 56

__device__ __forceinline__ void fma2(unsigned long long& acc,
                                     unsigned long long a,
                                     unsigned long long b) {
    asm("fma.rn.f32x2 %0, %1, %2, %0;" : "+l"(acc) : "l"(a), "l"(b));
}
__device__ __forceinline__ unsigned long long dup2(float x) {
    unsigned long long r;
    asm("mov.b64 %0, {%1, %1};" : "=l"(r) : "f"(x));
    return r;
}

// Single fused kernel. Block (bx, b, h) covers dims [h*128, (h+1)*128).
// Warp 0 computes per-batch Gaussian params (warp shfl-scan, no barriers)
// while warps 1..15 stage the embed-table slab — prep hides under staging.
// Lane owns float4 at h*128 + lane*4: conflict-free LDS, coalesced STG.
__global__ __launch_bounds__(NWARPS * 32, 2)
void ge_main_kernel(const int* __restrict__ text,
                    const int* __restrict__ durs,
                    const float* __restrict__ embed,
                    float* __restrict__ out, int Tt) {
    extern __shared__ float smem[];
    float* semb     = smem;                      // NVOCAB*DCH (51.2 KB)
    float* s_center = semb + NVOCAB * DCH;       // 256
    float* s_invsig = s_center + TC;             // 256
    float* s_wfac   = s_invsig + TC;             // 256
    int*   s_roff   = (int*)(s_wfac + TC);       // 256
    int*   s_fidx   = s_roff + TC;               // MAXT (8 KB)
    int*   s_td     = s_fidx + MAXT;             // 1 (totdur)
    float* s_wbuf   = (float*)(s_td + 4);        // NWARPS*FB*WMAX
    int*   s_cbuf   = (int*)(s_wbuf + NWARPS * FB * WMAX); // NWARPS*WMAX

    int tid = threadIdx.x;
    int b = blockIdx.y;
    int h = blockIdx.z;

    if (tid < 32) {
        // ---- in-block prep: warp-scan of durations, per-char params ----
        int lane = tid;
        const int4* dp = (const int4*)(durs + b * TC + lane * 8);
        int4 da = dp[0], db4 = dp[1];
        int dv[8] = {da.x, da.y, da.z, da.w, db4.x, db4.y, db4.z, db4.w};
        const int4* tp = (const int4*)(text + b * TC + lane * 8);
        int4 ta = tp[0], tb4 = tp[1];
        int tv[8] = {ta.x, ta.y, ta.z, ta.w, tb4.x, tb4.y, tb4.z, tb4.w};

        int lanesum = 0;
        #pragma unroll
        for (int i = 0; i < 8; i++) lanesum += dv[i];
        int incl = lanesum;
        #pragma unroll
        for (int off = 1; off < 32; off <<= 1) {
            int v = __shfl_up_sync(0xffffffffu, incl, off);
            if (lane >= off) incl += v;
        }
        int run = incl - lanesum;                // exclusive prefix

        #pragma unroll
        for (int i = 0; i < 8; i++) {
            int c = lane * 8 + i;
            int d = dv[i];
            float df = (float)d;
            float sig = df * 0.5f + 1e-6f;       // dur/SIGMA_C + EPS
            float is = 1.0f / sig;
            s_center[c] = (float)run + df * 0.5f;
            s_invsig[c] = is;
            s_wfac[c]   = 0.3989422804014327f * is;
            s_roff[c]   = tv[i] * DCH;
            for (int f = run; f < run + d; f++) s_fidx[f] = c;
            run += d;
        }
        if (lane == 31) *s_td = incl;
    } else {
        // ---- warps 1..15 stage the 128-dim table slab concurrently ----
        for (int i = tid - 32; i < NVOCAB * 32; i += (NWARPS - 1) * 32) {
            int v = i >> 5, c = i & 31;
            ((float4*)(semb + v * DCH))[c] =
                *((const float4*)(embed + v * ND + h * DCH) + c);
        }
    }
    __syncthreads();

    int totdur = *s_td;
    int wid = tid >> 5, lane = tid & 31;
    float* wrow4 = s_wbuf + wid * (FB * WMAX);
    int*   coffw = s_cbuf + wid * WMAX;

    for (int t0 = (blockIdx.x * NWARPS + wid) * FB; t0 < Tt;
         t0 += NTILES * NWARPS * FB) {

        int nvalid = totdur - t0;
        if (nvalid > FB) nvalid = FB;

        if (nvalid <= 0) {                       // whole group time-pad -> embed[0]
            float4 e0 = ((const float4*)semb)[lane];
            #pragma unroll
            for (int f = 0; f < FB; f++) {
                int t = t0 + f;
                if (t >= Tt) break;
                ((float4*)(out + ((size_t)b * Tt + t) * ND + h * DCH))[lane] = e0;
            }
            continue;
        }

        int lo = s_fidx[max(t0 - RWIN, 0)];
        int hi = s_fidx[min(t0 + FB - 1 + RWIN, totdur - 1)] + 1;
        int win = hi - lo;                       // <= 56

        // ---- weight pass (raw weights) ----
        float tt = (float)t0 + 0.5f;
        float l0 = 0.f, l1 = 0.f, l2 = 0.f, l3 = 0.f;
        for (int j = lane; j < win; j += 32) {
            int c = lo + j;
            float is = s_invsig[c];
            float z0 = (tt - s_center[c]) * is;
            float z1 = z0 + is, z2 = z1 + is, z3 = z2 + is;
            float wf = s_wfac[c];
            float w0 = __expf(-0.5f * z0 * z0) * wf;
            float w1 = __expf(-0.5f * z1 * z1) * wf;
            float w2 = __expf(-0.5f * z2 * z2) * wf;
            float w3 = __expf(-0.5f * z3 * z3) * wf;
            if (1 >= nvalid) w1 = 0.f;
            if (2 >= nvalid) w2 = 0.f;
            if (3 >= nvalid) w3 = 0.f;
            *(float4*)&wrow4[j * 4] = make_float4(w0, w1, w2, w3);
            l0 += w0; l1 += w1; l2 += w2; l3 += w3;
        }
        __syncwarp();
        #pragma unroll
        for (int off = 16; off; off >>= 1) {
            l0 += __shfl_xor_sync(0xffffffffu, l0, off);
            l1 += __shfl_xor_sync(0xffffffffu, l1, off);
            l2 += __shfl_xor_sync(0xffffffffu, l2, off);
            l3 += __shfl_xor_sync(0xffffffffu, l3, off);
        }
        float i0 = 1.0f / (l0 + 1e-6f), i1 = 1.0f / (l1 + 1e-6f);
        float i2 = 1.0f / (l2 + 1e-6f), i3 = 1.0f / (l3 + 1e-6f);

        // ---- normalize + compact ----
        int nact = 0;
        for (int base = 0; base < win; base += 32) {
            int j = base + lane;
            float4 wv;
            int off = 0;
            bool act = false;
            if (j < win) {
                wv = *(float4*)&wrow4[j * 4];
                wv.x *= i0; wv.y *= i1; wv.z *= i2; wv.w *= i3;
                act = (wv.x > 1e-8f) | (wv.y > 1e-8f) |
                      (wv.z > 1e-8f) | (wv.w > 1e-8f);
                off = s_roff[lo + j];
            }
            unsigned mask = __ballot_sync(0xffffffffu, act);
            __syncwarp();
            if (act) {
                int pos = nact + __popc(mask & ((1u << lane) - 1u));
                *(float4*)&wrow4[pos * 4] = wv;   // pos <= j, no clobber
                coffw[pos] = off;
            }
            nact += __popc(mask);
        }
        __syncwarp();

        // ---- branch-free FMA pass (R8 scheme: LDS + reg dup) ----
        unsigned long long A[FB][2];
        #pragma unroll
        for (int f = 0; f < FB; f++) { A[f][0] = 0ULL; A[f][1] = 0ULL; }

        for (int k = 0; k < nact; k++) {
            float4 wv = *(float4*)&wrow4[k * 4];  // LDS.128 broadcast
            int off = coffw[k];                    // LDS broadcast
            ulonglong2 p = ((const ulonglong2*)(semb + off))[lane];
            unsigned long long W0 = dup2(wv.x), W1 = dup2(wv.y);
            unsigned long long W2 = dup2(wv.z), W3 = dup2(wv.w);
            fma2(A[0][0], W0, p.x); fma2(A[0][1], W0, p.y);
            fma2(A[1][0], W1, p.x); fma2(A[1][1], W1, p.y);
            fma2(A[2][0], W2, p.x); fma2(A[2][1], W2, p.y);
            fma2(A[3][0], W3, p.x); fma2(A[3][1], W3, p.y);
        }
        __syncwarp();   // wrow4/coffw reused next group

        // ---- write (weights pre-normalized; coalesced 512B) ----
        #pragma unroll
        for (int f = 0; f < FB; f++) {
            int t = t0 + f;
            if (t >= Tt) break;
            float4* o = (float4*)(out + ((size_t)b * Tt + t) * ND + h * DCH);
            if (f < nvalid) {
                union { unsigned long long u[2]; float4 v; } cv;
                cv.u[0] = A[f][0];
                cv.u[1] = A[f][1];
                o[lane] = cv.v;
            } else {      // time-pad frame -> embed[0]
                o[lane] = ((const float4*)semb)[lane];
            }
        }
    }
}

extern "C" void kernel_launch(void* const* d_in, const int* in_sizes, int n_in,
                              void* d_out, int out_size) {
    const int*   text  = (const int*)d_in[0];
    const int*   durs  = (const int*)d_in[1];
    const float* embed = (const float*)d_in[2];
    float* out = (float*)d_out;

    int Tt = out_size / (NB * ND);

    size_t smem_bytes = (size_t)(NVOCAB * DCH + 3 * TC) * sizeof(float)
                        + (size_t)(TC + MAXT + 4) * sizeof(int)
                        + (size_t)(NWARPS * FB * WMAX) * sizeof(float)
                        + (size_t)(NWARPS * WMAX) * sizeof(int);
    cudaFuncSetAttribute(ge_main_kernel,
                         cudaFuncAttributeMaxDynamicSharedMemorySize,
                         (int)smem_bytes);

    ge_main_kernel<<<dim3(NTILES, NB, 3), NWARPS * 32, smem_bytes>>>(
        text, durs, embed, out, Tt);
}